// round 1
// baseline (speedup 1.0000x reference)
#include <cuda_runtime.h>
#include <math.h>

// ---------------------------------------------------------------------------
// GraphAE on GB300. pseudo == 0 => only spline weight k=0 contributes.
// Pipeline:
//   CSR build (hist/scan/place) -> agg1(gather x) -> G1 -> h
//   G2: h @ [W2|root2] -> [hW|hroot] -> agg2(gather hW) -> z
//   G3: z@dec_w1 relu -> h2 ; G4: h2@dec_w2 -> out
// ---------------------------------------------------------------------------

#define NNODES 50000
#define NEDGES 800000
#define NB_SCAN 49   // ceil(50000/1024)

// ------------------------- scratch (static device) -------------------------
__device__ int   g_cnt[NNODES];
__device__ int   g_rowptr[NNODES + 1];
__device__ int   g_cursor[NNODES];
__device__ int   g_csr[NEDGES];
__device__ float g_invdeg[NNODES];
__device__ int   g_scantmp[NNODES];
__device__ int   g_bsum[NB_SCAN];
__device__ int   g_boff[NB_SCAN];

__device__ float g_A1[(size_t)NNODES * 128];   // [agg1*invdeg | x]
__device__ float g_h[(size_t)NNODES * 256];    // relu(conv1)
__device__ float g_hWr[(size_t)NNODES * 128];  // [h@W2 | h@root2 + b2]
__device__ float g_z[(size_t)NNODES * 64];     // conv2 output
__device__ float g_h2[(size_t)NNODES * 256];   // relu(z@dec_w1+b)

__device__ float g_B1[128 * 256];              // [W1[0]; root1]
__device__ float g_B2[256 * 128];              // [W2[0] | root2]
__device__ float g_b2c[128];                   // [0 | conv2_b]

// ------------------------------ weight prep --------------------------------
__global__ void prep_k(const float* __restrict__ c1W, const float* __restrict__ c1r,
                       const float* __restrict__ c2W, const float* __restrict__ c2r,
                       const float* __restrict__ c2b) {
    int i = blockIdx.x * blockDim.x + threadIdx.x;
    if (i < 128 * 256) {
        g_B1[i] = (i < 64 * 256) ? c1W[i] : c1r[i - 64 * 256];
    }
    if (i < 256 * 128) {
        int k = i >> 7, j = i & 127;
        g_B2[i] = (j < 64) ? c2W[k * 64 + j] : c2r[k * 64 + (j - 64)];
    }
    if (i < 128) g_b2c[i] = (i < 64) ? 0.0f : c2b[i - 64];
}

// ------------------------------- CSR build ---------------------------------
__global__ void hist_k(const int* __restrict__ ei) {
    int e = blockIdx.x * blockDim.x + threadIdx.x;
    if (e < NEDGES) atomicAdd(&g_cnt[ei[NEDGES + e]], 1);
}

__global__ void scan1_k() {
    __shared__ int sh[1024];
    int i = blockIdx.x * 1024 + threadIdx.x;
    int v = (i < NNODES) ? g_cnt[i] : 0;
    sh[threadIdx.x] = v;
    __syncthreads();
    #pragma unroll
    for (int off = 1; off < 1024; off <<= 1) {
        int t = (threadIdx.x >= off) ? sh[threadIdx.x - off] : 0;
        __syncthreads();
        sh[threadIdx.x] += t;
        __syncthreads();
    }
    if (i < NNODES) g_scantmp[i] = sh[threadIdx.x];
    if (threadIdx.x == 1023) g_bsum[blockIdx.x] = sh[1023];
}

__global__ void scan2_k() {
    if (threadIdx.x == 0) {
        int acc = 0;
        for (int b = 0; b < NB_SCAN; b++) { g_boff[b] = acc; acc += g_bsum[b]; }
    }
}

__global__ void scan3_k() {
    int i = blockIdx.x * blockDim.x + threadIdx.x;
    if (i < NNODES) {
        int incl = g_scantmp[i] + g_boff[i >> 10];
        int c = g_cnt[i];
        int start = incl - c;
        g_rowptr[i] = start;
        g_cursor[i] = start;
        g_invdeg[i] = 1.0f / fmaxf((float)c, 1.0f);
        if (i == NNODES - 1) g_rowptr[NNODES] = incl;
    }
}

__global__ void place_k(const int* __restrict__ ei) {
    int e = blockIdx.x * blockDim.x + threadIdx.x;
    if (e < NEDGES) {
        int d = ei[NEDGES + e];
        int p = atomicAdd(&g_cursor[d], 1);
        g_csr[p] = ei[e];  // src
    }
}

// --------------------------- gather aggregations ---------------------------
// warp per node; lane handles feature c=lane and c=lane+32 (64-dim payload)
__global__ void agg1_k(const float* __restrict__ x) {
    int gt = blockIdx.x * blockDim.x + threadIdx.x;
    int node = gt >> 5;
    if (node >= NNODES) return;
    int lane = gt & 31;
    int beg = g_rowptr[node], end = g_rowptr[node + 1];
    float s0 = 0.f, s1 = 0.f;
    for (int i = beg; i < end; i++) {
        int s = g_csr[i];
        const float* r = x + (size_t)s * 64;
        s0 += __ldg(&r[lane]);
        s1 += __ldg(&r[lane + 32]);
    }
    float iv = g_invdeg[node];
    float* o = g_A1 + (size_t)node * 128;
    const float* xr = x + (size_t)node * 64;
    o[lane]      = s0 * iv;
    o[lane + 32] = s1 * iv;
    o[lane + 64] = xr[lane];
    o[lane + 96] = xr[lane + 32];
}

// z = gather(hW)*invdeg + hroot   (hW = cols 0:64 of g_hWr, hroot = 64:128)
__global__ void agg2_k() {
    int gt = blockIdx.x * blockDim.x + threadIdx.x;
    int node = gt >> 5;
    if (node >= NNODES) return;
    int lane = gt & 31;
    int beg = g_rowptr[node], end = g_rowptr[node + 1];
    float s0 = 0.f, s1 = 0.f;
    for (int i = beg; i < end; i++) {
        int s = g_csr[i];
        const float* r = g_hWr + (size_t)s * 128;
        s0 += __ldg(&r[lane]);
        s1 += __ldg(&r[lane + 32]);
    }
    float iv = g_invdeg[node];
    const float* own = g_hWr + (size_t)node * 128;
    g_z[(size_t)node * 64 + lane]      = s0 * iv + own[64 + lane];
    g_z[(size_t)node * 64 + lane + 32] = s1 * iv + own[96 + lane];
}

// ------------------------------- FP32 GEMM ---------------------------------
// C[n, NC] = op(A[n,K] @ B[K,NC] + bias), 64 rows per block, 256 threads.
// Whole B staged in smem (weights), A tile staged in smem.
// Thread (tx,ty): rows ty*8..+7, cols tx*CPT..+CPT-1.
template <int K, int NC, bool RELU>
__global__ void gemm_k(const float* __restrict__ A, const float* __restrict__ B,
                       const float* __restrict__ bias, float* __restrict__ C,
                       int nRows) {
    constexpr int CPT = NC / 32;
    extern __shared__ float sm[];
    float* Bs = sm;               // K*NC
    float* As = sm + K * NC;      // 64*K

    int tid = threadIdx.x;
    int n0 = blockIdx.x * 64;
    int rem = nRows - n0;

    // stage B (weights)
    {
        const float4* B4 = (const float4*)B;
        float4* Bs4 = (float4*)Bs;
        for (int i = tid; i < K * NC / 4; i += 256) Bs4[i] = B4[i];
    }
    // stage A tile (row-clamped for the partial last block)
    {
        const float4* A4 = (const float4*)A;
        float4* As4 = (float4*)As;
        for (int i = tid; i < 64 * K / 4; i += 256) {
            int row = (i * 4) / K;
            int col4 = i - row * (K / 4);
            int r = (row < rem) ? row : (rem - 1);
            As4[i] = A4[(size_t)(n0 + r) * (K / 4) + col4];
        }
    }
    __syncthreads();

    int tx = tid & 31, ty = tid >> 5;
    float acc[8][CPT];
    #pragma unroll
    for (int i = 0; i < 8; i++)
        #pragma unroll
        for (int j = 0; j < CPT; j++) acc[i][j] = 0.f;

    #pragma unroll 4
    for (int k = 0; k < K; k++) {
        float a[8];
        #pragma unroll
        for (int i = 0; i < 8; i++) a[i] = As[(ty * 8 + i) * K + k];
        float b[CPT];
        #pragma unroll
        for (int j = 0; j < CPT; j++) b[j] = Bs[k * NC + tx * CPT + j];
        #pragma unroll
        for (int i = 0; i < 8; i++)
            #pragma unroll
            for (int j = 0; j < CPT; j++) acc[i][j] = fmaf(a[i], b[j], acc[i][j]);
    }

    // epilogue
    float bv[CPT];
    #pragma unroll
    for (int j = 0; j < CPT; j++) bv[j] = __ldg(&bias[tx * CPT + j]);
    #pragma unroll
    for (int i = 0; i < 8; i++) {
        int row = ty * 8 + i;
        if (row < rem) {
            float* cr = C + (size_t)(n0 + row) * NC + tx * CPT;
            #pragma unroll
            for (int j = 0; j < CPT; j++) {
                float v = acc[i][j] + bv[j];
                if (RELU) v = fmaxf(v, 0.f);
                cr[j] = v;
            }
        }
    }
}

// ------------------------------- launcher ----------------------------------
extern "C" void kernel_launch(void* const* d_in, const int* in_sizes, int n_in,
                              void* d_out, int out_size) {
    const float* x   = (const float*)d_in[0];
    const int*   ei  = (const int*)d_in[1];
    const float* c1W = (const float*)d_in[2];
    const float* c1r = (const float*)d_in[3];
    const float* c1b = (const float*)d_in[4];
    const float* c2W = (const float*)d_in[5];
    const float* c2r = (const float*)d_in[6];
    const float* c2b = (const float*)d_in[7];
    const float* dw1 = (const float*)d_in[8];
    const float* db1 = (const float*)d_in[9];
    const float* dw2 = (const float*)d_in[10];
    const float* db2 = (const float*)d_in[11];
    float* out = (float*)d_out;

    // symbol addresses (host API, not stream work -> capture safe)
    void *pCnt, *pA1, *pH, *pHWr, *pZ, *pH2, *pB1, *pB2, *pB2c;
    cudaGetSymbolAddress(&pCnt, g_cnt);
    cudaGetSymbolAddress(&pA1, g_A1);
    cudaGetSymbolAddress(&pH, g_h);
    cudaGetSymbolAddress(&pHWr, g_hWr);
    cudaGetSymbolAddress(&pZ, g_z);
    cudaGetSymbolAddress(&pH2, g_h2);
    cudaGetSymbolAddress(&pB1, g_B1);
    cudaGetSymbolAddress(&pB2, g_B2);
    cudaGetSymbolAddress(&pB2c, g_b2c);

    // opt-in shared mem for the big GEMM tiles (idempotent)
    const int SM_G1 = (128 * 256 + 64 * 128) * 4;  // 160KB
    const int SM_G2 = (256 * 128 + 64 * 256) * 4;  // 192KB
    const int SM_G3 = (64 * 256 + 64 * 64) * 4;    // 80KB
    const int SM_G4 = (256 * 64 + 64 * 256) * 4;   // 128KB
    cudaFuncSetAttribute(gemm_k<128, 256, true>,  cudaFuncAttributeMaxDynamicSharedMemorySize, SM_G1);
    cudaFuncSetAttribute(gemm_k<256, 128, false>, cudaFuncAttributeMaxDynamicSharedMemorySize, SM_G2);
    cudaFuncSetAttribute(gemm_k<64, 256, true>,   cudaFuncAttributeMaxDynamicSharedMemorySize, SM_G3);
    cudaFuncSetAttribute(gemm_k<256, 64, false>,  cudaFuncAttributeMaxDynamicSharedMemorySize, SM_G4);

    const int nGemmBlocks = (NNODES + 63) / 64;          // 782
    const int nEdgeBlocks = (NEDGES + 255) / 256;        // 3125
    const int nAggBlocks  = (NNODES * 32 + 255) / 256;   // 6250
    const int nNodeBlocks = (NNODES + 255) / 256;

    // --- CSR build ---
    cudaMemsetAsync(pCnt, 0, NNODES * sizeof(int));
    prep_k<<<(256 * 128 + 255) / 256, 256>>>(c1W, c1r, c2W, c2r, c2b);
    hist_k<<<nEdgeBlocks, 256>>>(ei);
    scan1_k<<<NB_SCAN, 1024>>>();
    scan2_k<<<1, 32>>>();
    scan3_k<<<nNodeBlocks, 256>>>();
    place_k<<<nEdgeBlocks, 256>>>(ei);

    // --- conv1 ---
    agg1_k<<<nAggBlocks, 256>>>(x);
    gemm_k<128, 256, true><<<nGemmBlocks, 256, SM_G1>>>(
        (const float*)pA1, (const float*)pB1, c1b, (float*)pH, NNODES);

    // --- conv2 (scatter h@W2 instead of h: 64-dim edge payload) ---
    gemm_k<256, 128, false><<<nGemmBlocks, 256, SM_G2>>>(
        (const float*)pH, (const float*)pB2, (const float*)pB2c, (float*)pHWr, NNODES);
    agg2_k<<<nAggBlocks, 256>>>();

    // --- decoder ---
    gemm_k<64, 256, true><<<nGemmBlocks, 256, SM_G3>>>(
        (const float*)pZ, dw1, db1, (float*)pH2, NNODES);
    gemm_k<256, 64, false><<<nGemmBlocks, 256, SM_G4>>>(
        (const float*)pH2, dw2, db2, out, NNODES);
}

// round 3
// speedup vs baseline: 2.3474x; 2.3474x over previous
#include <cuda_runtime.h>
#include <cuda_bf16.h>
#include <math.h>
#include <stdint.h>

// ---------------------------------------------------------------------------
// GraphAE on GB300 (sm_103 PTX target -> legacy mma.sync tensor path).
// pseudo == 0 => only spline weight k=0 contributes.
//   CSR build -> agg1(gather x) -> G1 -> h
//   G2: h @ [W2|root2] -> [hW|hroot] -> agg2(gather hW) -> z
//   G3: z@dec_w1 relu -> h2 ; G4: h2@dec_w2 -> out
// GEMMs: bf16 mma.sync.m16n8k16 with hi/lo split (3 products, fp32 accum).
// ---------------------------------------------------------------------------

#define NNODES 50000
#define NEDGES 800000
#define NB_SCAN 49

// ------------------------- scratch (static device) -------------------------
__device__ int   g_cnt[NNODES];
__device__ int   g_rowptr[NNODES + 1];
__device__ int   g_cursor[NNODES];
__device__ int   g_csr[NEDGES];
__device__ float g_invdeg[NNODES];
__device__ int   g_scantmp[NNODES];
__device__ int   g_bsum[NB_SCAN];
__device__ int   g_boff[NB_SCAN];

__device__ float g_A1[(size_t)NNODES * 128];   // [agg1*invdeg | x]
__device__ float g_h[(size_t)NNODES * 256];    // relu(conv1)
__device__ float g_hWr[(size_t)NNODES * 128];  // [h@W2 | h@root2 + b2]
__device__ float g_z[(size_t)NNODES * 64];     // conv2 output
__device__ float g_h2[(size_t)NNODES * 256];   // relu(z@dec_w1+b)

// bf16 hi/lo split weights, natural [k][n] row-major
__device__ __nv_bfloat16 g_B1h[128 * 256], g_B1l[128 * 256];
__device__ __nv_bfloat16 g_B2h[256 * 128], g_B2l[256 * 128];
__device__ __nv_bfloat16 g_D1h[64 * 256],  g_D1l[64 * 256];
__device__ __nv_bfloat16 g_D2h[256 * 64],  g_D2l[256 * 64];
__device__ float g_b2c[128];                   // [0 | conv2_b]

// ------------------------------ helpers ------------------------------------
__device__ __forceinline__ uint32_t smem_u32(const void* p) {
    uint32_t a;
    asm("{ .reg .u64 t; cvta.to.shared.u64 t, %1; cvt.u32.u64 %0, t; }"
        : "=r"(a) : "l"(p));
    return a;
}

__device__ __forceinline__ void ldsm_x4(uint32_t* r, uint32_t addr) {
    asm volatile("ldmatrix.sync.aligned.m8n8.x4.shared.b16 {%0,%1,%2,%3}, [%4];"
                 : "=r"(r[0]), "=r"(r[1]), "=r"(r[2]), "=r"(r[3]) : "r"(addr));
}
__device__ __forceinline__ void ldsm_x4t(uint32_t* r, uint32_t addr) {
    asm volatile("ldmatrix.sync.aligned.m8n8.x4.trans.shared.b16 {%0,%1,%2,%3}, [%4];"
                 : "=r"(r[0]), "=r"(r[1]), "=r"(r[2]), "=r"(r[3]) : "r"(addr));
}
__device__ __forceinline__ void mma_bf16(float* d, const uint32_t* a,
                                         uint32_t b0, uint32_t b1) {
    asm volatile("mma.sync.aligned.m16n8k16.row.col.f32.bf16.bf16.f32 "
                 "{%0,%1,%2,%3}, {%4,%5,%6,%7}, {%8,%9}, {%0,%1,%2,%3};"
                 : "+f"(d[0]), "+f"(d[1]), "+f"(d[2]), "+f"(d[3])
                 : "r"(a[0]), "r"(a[1]), "r"(a[2]), "r"(a[3]), "r"(b0), "r"(b1));
}

__device__ __forceinline__ void split1(float v, uint16_t& h, uint16_t& l) {
    __nv_bfloat16 hb = __float2bfloat16_rn(v);
    float r = v - __bfloat162float(hb);
    __nv_bfloat16 lb = __float2bfloat16_rn(r);
    h = __bfloat16_as_ushort(hb);
    l = __bfloat16_as_ushort(lb);
}

// ------------------------------ weight prep --------------------------------
__global__ void prep_k(const float* __restrict__ c1W, const float* __restrict__ c1r,
                       const float* __restrict__ c2W, const float* __restrict__ c2r,
                       const float* __restrict__ c2b,
                       const float* __restrict__ dw1, const float* __restrict__ dw2) {
    int i = blockIdx.x * blockDim.x + threadIdx.x;
    uint16_t h, l;
    if (i < 128 * 256) {  // B1 [k=128][n=256]
        int k = i >> 8, n = i & 255;
        float v = (k < 64) ? c1W[k * 256 + n] : c1r[(k - 64) * 256 + n];
        split1(v, h, l);
        g_B1h[i] = __ushort_as_bfloat16(h); g_B1l[i] = __ushort_as_bfloat16(l);
    }
    if (i < 256 * 128) {  // B2 [k=256][n=128]
        int k = i >> 7, n = i & 127;
        float v = (n < 64) ? c2W[k * 64 + n] : c2r[k * 64 + (n - 64)];
        split1(v, h, l);
        g_B2h[i] = __ushort_as_bfloat16(h); g_B2l[i] = __ushort_as_bfloat16(l);
    }
    if (i < 64 * 256) {   // D1 [k=64][n=256]
        split1(dw1[i], h, l);
        g_D1h[i] = __ushort_as_bfloat16(h); g_D1l[i] = __ushort_as_bfloat16(l);
    }
    if (i < 256 * 64) {   // D2 [k=256][n=64]
        split1(dw2[i], h, l);
        g_D2h[i] = __ushort_as_bfloat16(h); g_D2l[i] = __ushort_as_bfloat16(l);
    }
    if (i < 128) g_b2c[i] = (i < 64) ? 0.0f : c2b[i - 64];
}

// ------------------------------- CSR build ---------------------------------
__global__ void hist_k(const int* __restrict__ ei) {
    int e = blockIdx.x * blockDim.x + threadIdx.x;
    if (e < NEDGES) atomicAdd(&g_cnt[ei[NEDGES + e]], 1);
}

__global__ void scan1_k() {
    __shared__ int sh[1024];
    int i = blockIdx.x * 1024 + threadIdx.x;
    int v = (i < NNODES) ? g_cnt[i] : 0;
    sh[threadIdx.x] = v;
    __syncthreads();
    #pragma unroll
    for (int off = 1; off < 1024; off <<= 1) {
        int t = (threadIdx.x >= off) ? sh[threadIdx.x - off] : 0;
        __syncthreads();
        sh[threadIdx.x] += t;
        __syncthreads();
    }
    if (i < NNODES) g_scantmp[i] = sh[threadIdx.x];
    if (threadIdx.x == 1023) g_bsum[blockIdx.x] = sh[1023];
}

__global__ void scan2_k() {
    __shared__ int sh[64];
    int i = threadIdx.x;
    int v = (i < NB_SCAN) ? g_bsum[i] : 0;
    sh[i] = v;
    __syncthreads();
    #pragma unroll
    for (int off = 1; off < 64; off <<= 1) {
        int t = (i >= off) ? sh[i - off] : 0;
        __syncthreads();
        sh[i] += t;
        __syncthreads();
    }
    if (i < NB_SCAN) g_boff[i] = sh[i] - v;
}

__global__ void scan3_k() {
    int i = blockIdx.x * blockDim.x + threadIdx.x;
    if (i < NNODES) {
        int incl = g_scantmp[i] + g_boff[i >> 10];
        int c = g_cnt[i];
        int start = incl - c;
        g_rowptr[i] = start;
        g_cursor[i] = start;
        g_invdeg[i] = 1.0f / fmaxf((float)c, 1.0f);
        if (i == NNODES - 1) g_rowptr[NNODES] = incl;
    }
}

__global__ void place_k(const int* __restrict__ ei) {
    int e = blockIdx.x * blockDim.x + threadIdx.x;
    if (e < NEDGES) {
        int d = ei[NEDGES + e];
        int p = atomicAdd(&g_cursor[d], 1);
        g_csr[p] = ei[e];  // src
    }
}

// --------------------------- gather aggregations ---------------------------
__global__ void agg1_k(const float* __restrict__ x) {
    int gt = blockIdx.x * blockDim.x + threadIdx.x;
    int node = gt >> 5;
    if (node >= NNODES) return;
    int lane = gt & 31;
    int beg = g_rowptr[node], end = g_rowptr[node + 1];
    float s0 = 0.f, s1 = 0.f;
    for (int i = beg; i < end; i++) {
        int s = g_csr[i];
        const float* r = x + (size_t)s * 64;
        s0 += __ldg(&r[lane]);
        s1 += __ldg(&r[lane + 32]);
    }
    float iv = g_invdeg[node];
    float* o = g_A1 + (size_t)node * 128;
    const float* xr = x + (size_t)node * 64;
    o[lane]      = s0 * iv;
    o[lane + 32] = s1 * iv;
    o[lane + 64] = xr[lane];
    o[lane + 96] = xr[lane + 32];
}

__global__ void agg2_k() {
    int gt = blockIdx.x * blockDim.x + threadIdx.x;
    int node = gt >> 5;
    if (node >= NNODES) return;
    int lane = gt & 31;
    int beg = g_rowptr[node], end = g_rowptr[node + 1];
    float s0 = 0.f, s1 = 0.f;
    for (int i = beg; i < end; i++) {
        int s = g_csr[i];
        const float* r = g_hWr + (size_t)s * 128;
        s0 += __ldg(&r[lane]);
        s1 += __ldg(&r[lane + 32]);
    }
    float iv = g_invdeg[node];
    const float* own = g_hWr + (size_t)node * 128;
    g_z[(size_t)node * 64 + lane]      = s0 * iv + own[64 + lane];
    g_z[(size_t)node * 64 + lane + 32] = s1 * iv + own[96 + lane];
}

// ------------------------ bf16 mma.sync GEMM -------------------------------
// C[128, NC] per CTA = op(A[.,K] @ B[K,NC] + bias). 8 warps in 4(m)x2(n).
// Warp tile: 32 rows x NC/2 cols. K staged in chunks of 32 (hi/lo bf16).
// Error-compensated: acc += Ah*Bh + Ah*Bl + Al*Bh (fp32 accum).
template <int K, int NC, bool RELU>
__global__ void __launch_bounds__(256, 1)
mgemm_k(const float* __restrict__ A,
        const __nv_bfloat16* __restrict__ Bh, const __nv_bfloat16* __restrict__ Bl,
        const float* __restrict__ bias, float* __restrict__ C, int nRows) {
    constexpr int KC = 32;
    constexpr int PA = 56;        // A smem row stride (elems): 112B, LDSM conflict-free
    constexpr int SB = NC + 8;    // B smem row stride (elems)
    constexpr int OAH = 0;
    constexpr int OAL = 128 * PA * 2;            // 14336
    constexpr int OBH = OAL * 2;                 // 28672
    constexpr int OBL = OBH + KC * SB * 2;
    constexpr int NT  = NC / 16;  // n8 tiles per warp (NC/2 cols / 8)
    constexpr int NTG = NC / 32;  // n16 ldmatrix groups per warp

    extern __shared__ char dsm[];
    uint32_t sbase = smem_u32(dsm);

    const int tid = threadIdx.x;
    const int wid = tid >> 5, lane = tid & 31;
    const int wm = wid & 3, wn = wid >> 2;
    const int col0 = wn * (NC / 2);
    const int n0 = blockIdx.x * 128;
    int rem = nRows - n0;
    if (rem > 128) rem = 128;

    float acc[2][NT][4];
    #pragma unroll
    for (int mt = 0; mt < 2; mt++)
        #pragma unroll
        for (int j = 0; j < NT; j++)
            #pragma unroll
            for (int q = 0; q < 4; q++) acc[mt][j][q] = 0.f;

    // per-thread ldmatrix base components
    const int lrow = lane & 15, lhalf = lane >> 4;

    for (int chunk = 0; chunk < K / KC; chunk++) {
        const int c0 = chunk * KC;
        // ---- stage A chunk: 128 x 32 floats -> bf16 hi/lo smem ----
        {
            const int r0 = tid >> 3;            // 0..31
            const int c4 = (tid & 7) << 2;      // 0,4,..28
            #pragma unroll
            for (int it = 0; it < 4; it++) {
                int row = it * 32 + r0;
                int gr = n0 + (row < rem ? row : rem - 1);
                float4 a = *(const float4*)(A + (size_t)gr * K + c0 + c4);
                uint16_t hx, lx, hy, ly, hz, lz, hw, lw;
                split1(a.x, hx, lx); split1(a.y, hy, ly);
                split1(a.z, hz, lz); split1(a.w, hw, lw);
                uint2 hv, lv;
                hv.x = (uint32_t)hx | ((uint32_t)hy << 16);
                hv.y = (uint32_t)hz | ((uint32_t)hw << 16);
                lv.x = (uint32_t)lx | ((uint32_t)ly << 16);
                lv.y = (uint32_t)lz | ((uint32_t)lw << 16);
                int off = (row * PA + c4) * 2;
                *(uint2*)(dsm + OAH + off) = hv;
                *(uint2*)(dsm + OAL + off) = lv;
            }
        }
        // ---- stage B chunk: 32 x NC bf16 (pre-split) ----
        {
            constexpr int G8 = NC / 8;          // 16B groups per row
            #pragma unroll
            for (int it = 0; it < (KC * G8 + 255) / 256; it++) {
                int idx = it * 256 + tid;
                if (KC * G8 % 256 == 0 || idx < KC * G8) {
                    int row = idx / G8, g8 = idx - row * G8;
                    size_t gsrc = (size_t)(c0 + row) * NC + g8 * 8;
                    uint4 hv = *(const uint4*)(Bh + gsrc);
                    uint4 lv = *(const uint4*)(Bl + gsrc);
                    int off = (row * SB + g8 * 8) * 2;
                    *(uint4*)(dsm + OBH + off) = hv;
                    *(uint4*)(dsm + OBL + off) = lv;
                }
            }
        }
        __syncthreads();

        // ---- compute ----
        #pragma unroll
        for (int kk = 0; kk < KC; kk += 16) {
            uint32_t ah[2][4], al[2][4];
            #pragma unroll
            for (int mt = 0; mt < 2; mt++) {
                uint32_t ra = sbase + OAH +
                    (uint32_t)(((32 * wm + 16 * mt + lrow) * PA + kk) * 2 + lhalf * 16);
                ldsm_x4(ah[mt], ra);
                ldsm_x4(al[mt], ra + (OAL - OAH));
            }
            #pragma unroll
            for (int ng = 0; ng < NTG; ng++) {
                uint32_t rb = sbase + OBH +
                    (uint32_t)((((kk + lrow) * SB) + col0 + ng * 16) * 2 + lhalf * 16);
                uint32_t bh[4], bl[4];
                ldsm_x4t(bh, rb);
                ldsm_x4t(bl, rb + (OBL - OBH));
                #pragma unroll
                for (int mt = 0; mt < 2; mt++) {
                    mma_bf16(acc[mt][2 * ng],     ah[mt], bh[0], bh[1]);
                    mma_bf16(acc[mt][2 * ng],     ah[mt], bl[0], bl[1]);
                    mma_bf16(acc[mt][2 * ng],     al[mt], bh[0], bh[1]);
                    mma_bf16(acc[mt][2 * ng + 1], ah[mt], bh[2], bh[3]);
                    mma_bf16(acc[mt][2 * ng + 1], ah[mt], bl[2], bl[3]);
                    mma_bf16(acc[mt][2 * ng + 1], al[mt], bh[2], bh[3]);
                }
            }
        }
        __syncthreads();
    }

    // ---- epilogue ----
    const int qr = lane >> 2;          // 0..7
    const int qc = (lane & 3) << 1;    // 0,2,4,6
    #pragma unroll
    for (int mt = 0; mt < 2; mt++) {
        int row0 = 32 * wm + 16 * mt + qr;
        int row1 = row0 + 8;
        #pragma unroll
        for (int j = 0; j < NT; j++) {
            int col = col0 + 8 * j + qc;
            float b0 = __ldg(&bias[col]), b1 = __ldg(&bias[col + 1]);
            float2 v0, v1;
            v0.x = acc[mt][j][0] + b0; v0.y = acc[mt][j][1] + b1;
            v1.x = acc[mt][j][2] + b0; v1.y = acc[mt][j][3] + b1;
            if (RELU) {
                v0.x = fmaxf(v0.x, 0.f); v0.y = fmaxf(v0.y, 0.f);
                v1.x = fmaxf(v1.x, 0.f); v1.y = fmaxf(v1.y, 0.f);
            }
            if (row0 < rem) *(float2*)(C + (size_t)(n0 + row0) * NC + col) = v0;
            if (row1 < rem) *(float2*)(C + (size_t)(n0 + row1) * NC + col) = v1;
        }
    }
}

// ------------------------------- launcher ----------------------------------
extern "C" void kernel_launch(void* const* d_in, const int* in_sizes, int n_in,
                              void* d_out, int out_size) {
    const float* x   = (const float*)d_in[0];
    const int*   ei  = (const int*)d_in[1];
    const float* c1W = (const float*)d_in[2];
    const float* c1r = (const float*)d_in[3];
    const float* c1b = (const float*)d_in[4];
    const float* c2W = (const float*)d_in[5];
    const float* c2r = (const float*)d_in[6];
    const float* c2b = (const float*)d_in[7];
    const float* dw1 = (const float*)d_in[8];
    const float* db1 = (const float*)d_in[9];
    const float* dw2 = (const float*)d_in[10];
    const float* db2 = (const float*)d_in[11];
    float* out = (float*)d_out;

    void *pCnt, *pA1, *pH, *pHWr, *pZ, *pH2, *pB2c;
    void *pB1h, *pB1l, *pB2h, *pB2l, *pD1h, *pD1l, *pD2h, *pD2l;
    cudaGetSymbolAddress(&pCnt, g_cnt);
    cudaGetSymbolAddress(&pA1, g_A1);
    cudaGetSymbolAddress(&pH, g_h);
    cudaGetSymbolAddress(&pHWr, g_hWr);
    cudaGetSymbolAddress(&pZ, g_z);
    cudaGetSymbolAddress(&pH2, g_h2);
    cudaGetSymbolAddress(&pB2c, g_b2c);
    cudaGetSymbolAddress(&pB1h, g_B1h); cudaGetSymbolAddress(&pB1l, g_B1l);
    cudaGetSymbolAddress(&pB2h, g_B2h); cudaGetSymbolAddress(&pB2l, g_B2l);
    cudaGetSymbolAddress(&pD1h, g_D1h); cudaGetSymbolAddress(&pD1l, g_D1l);
    cudaGetSymbolAddress(&pD2h, g_D2h); cudaGetSymbolAddress(&pD2l, g_D2l);

    // dynamic smem: 28672 (A hi/lo) + 2*32*(NC+8)*2 (B hi/lo)
    const int SM_N256 = 28672 + 2 * 32 * 264 * 2;  // 62464
    const int SM_N128 = 28672 + 2 * 32 * 136 * 2;  // 46080
    const int SM_N64  = 28672 + 2 * 32 * 72 * 2;   // 37888
    cudaFuncSetAttribute(mgemm_k<128, 256, true>,  cudaFuncAttributeMaxDynamicSharedMemorySize, SM_N256);
    cudaFuncSetAttribute(mgemm_k<256, 128, false>, cudaFuncAttributeMaxDynamicSharedMemorySize, SM_N128);
    cudaFuncSetAttribute(mgemm_k<64, 256, true>,   cudaFuncAttributeMaxDynamicSharedMemorySize, SM_N256);
    cudaFuncSetAttribute(mgemm_k<256, 64, false>,  cudaFuncAttributeMaxDynamicSharedMemorySize, SM_N64);

    const int nTG = (NNODES + 127) / 128;               // 391
    const int nEdgeBlocks = (NEDGES + 255) / 256;
    const int nAggBlocks  = (NNODES * 32 + 255) / 256;
    const int nNodeBlocks = (NNODES + 255) / 256;

    // --- CSR build + weight prep ---
    cudaMemsetAsync(pCnt, 0, NNODES * sizeof(int));
    prep_k<<<128, 256>>>(c1W, c1r, c2W, c2r, c2b, dw1, dw2);
    hist_k<<<nEdgeBlocks, 256>>>(ei);
    scan1_k<<<NB_SCAN, 1024>>>();
    scan2_k<<<1, 64>>>();
    scan3_k<<<nNodeBlocks, 256>>>();
    place_k<<<nEdgeBlocks, 256>>>(ei);

    // --- conv1 ---
    agg1_k<<<nAggBlocks, 256>>>(x);
    mgemm_k<128, 256, true><<<nTG, 256, SM_N256>>>(
        (const float*)pA1, (const __nv_bfloat16*)pB1h, (const __nv_bfloat16*)pB1l,
        c1b, (float*)pH, NNODES);

    // --- conv2 (scatter h@W2 instead of h) ---
    mgemm_k<256, 128, false><<<nTG, 256, SM_N128>>>(
        (const float*)pH, (const __nv_bfloat16*)pB2h, (const __nv_bfloat16*)pB2l,
        (const float*)pB2c, (float*)pHWr, NNODES);
    agg2_k<<<nAggBlocks, 256>>>();

    // --- decoder ---
    mgemm_k<64, 256, true><<<nTG, 256, SM_N256>>>(
        (const float*)pZ, (const __nv_bfloat16*)pD1h, (const __nv_bfloat16*)pD1l,
        db1, (float*)pH2, NNODES);
    mgemm_k<256, 64, false><<<nTG, 256, SM_N64>>>(
        (const float*)pH2, (const __nv_bfloat16*)pD2h, (const __nv_bfloat16*)pD2l,
        db2, out, NNODES);
}